// round 5
// baseline (speedup 1.0000x reference)
#include <cuda_runtime.h>
#include <math.h>

#define NN 100000
#define EE 1600000
#define ET (EE + NN)
#define SLOPE 0.2f

// ---------------- scratch (static device globals; no runtime allocation) ----------------
__device__ __align__(16) float g_h[NN * 128];     // transformed features (x @ W)
__device__ __align__(16) float g_feat[NN * 128];  // layer activations (post bias+ELU)
__device__ __align__(16) float g_as[NN * 4];      // per-node attention src scalar (per head)
__device__ __align__(16) float g_ad[NN * 4];      // per-node attention dst scalar (per head)
__device__ int g_off[NN + 1];                     // CSR offsets (by dst)
__device__ int g_cur[NN];                         // scatter cursors
__device__ int g_csr[ET];                         // CSR: src index per incoming edge

// ---------------- CSR build ----------------
__global__ void k_init() {
    int i = blockIdx.x * blockDim.x + threadIdx.x;
    if (i < NN) g_off[i] = 1;  // self loop
}

__global__ void k_count(const int* __restrict__ dst) {
    int i = blockIdx.x * blockDim.x + threadIdx.x;
    if (i < EE) atomicAdd(&g_off[dst[i]], 1);
}

// single-block exclusive scan over g_off[0..NN-1], in place; writes g_cur too.
__global__ void k_scan() {
    __shared__ int swarp[32];
    __shared__ int s_carry;
    int t = threadIdx.x, lane = t & 31, wid = t >> 5;
    if (t == 0) s_carry = 0;
    __syncthreads();
    for (int base = 0; base < NN; base += 1024) {
        int i = base + t;
        int v = (i < NN) ? g_off[i] : 0;
        int c = s_carry;
        int x = v;
#pragma unroll
        for (int o = 1; o < 32; o <<= 1) {
            int y = __shfl_up_sync(0xffffffffu, x, o);
            if (lane >= o) x += y;
        }
        if (lane == 31) swarp[wid] = x;
        __syncthreads();
        if (wid == 0) {
            int y = swarp[lane];
#pragma unroll
            for (int o = 1; o < 32; o <<= 1) {
                int z = __shfl_up_sync(0xffffffffu, y, o);
                if (lane >= o) y += z;
            }
            swarp[lane] = y;
        }
        __syncthreads();
        int incl = x + ((wid > 0) ? swarp[wid - 1] : 0) + c;
        int excl = incl - v;
        if (i < NN) { g_off[i] = excl; g_cur[i] = excl; }
        __syncthreads();
        if (t == 0) s_carry = c + swarp[31];
        __syncthreads();
    }
    if (threadIdx.x == 0) g_off[NN] = s_carry;  // = ET
}

__global__ void k_scatter(const int* __restrict__ src, const int* __restrict__ dst) {
    int i = blockIdx.x * blockDim.x + threadIdx.x;
    if (i < ET) {
        int s, d;
        if (i < EE) { s = src[i]; d = dst[i]; }
        else        { s = i - EE; d = s; }
        int pos = atomicAdd(&g_cur[d], 1);
        g_csr[pos] = s;
    }
}

// ---------------- GEMM: H[n,128] = X[n,128] @ W[128,128] ----------------
// W fully resident in SMEM (64KB) + 64-row X tile (32KB). 256 threads.
// thread t: cols (t&31)*4..+3, rows blockRow + (t>>5)*8 .. +7  (32 outputs)
__global__ void k_gemm(const float* __restrict__ X, const float* __restrict__ W,
                       float* __restrict__ Hout) {
    extern __shared__ float sm[];
    float* Ws = sm;            // 16384 floats
    float* Xs = sm + 16384;    // 8192 floats
    int t = threadIdx.x;
    int rbase = blockIdx.x * 64;

    const float4* W4 = (const float4*)W;
    float4* Ws4 = (float4*)Ws;
#pragma unroll
    for (int i = 0; i < 16; i++) Ws4[t + i * 256] = W4[t + i * 256];

    const float4* X4 = (const float4*)X;
    float4* Xs4 = (float4*)Xs;
#pragma unroll
    for (int i = 0; i < 8; i++) {
        int idx = t + i * 256;           // float4 idx in tile; row=idx>>5, col4=idx&31
        int r = rbase + (idx >> 5);
        float4 v = make_float4(0.f, 0.f, 0.f, 0.f);
        if (r < NN) v = X4[r * 32 + (idx & 31)];
        Xs4[idx] = v;
    }
    __syncthreads();

    int colg = t & 31;
    int rg = t >> 5;
    float acc[8][4];
#pragma unroll
    for (int i = 0; i < 8; i++)
#pragma unroll
        for (int j = 0; j < 4; j++) acc[i][j] = 0.f;

#pragma unroll 2
    for (int k = 0; k < 128; k++) {
        float4 w = Ws4[k * 32 + colg];
#pragma unroll
        for (int i = 0; i < 8; i++) {
            float xv = Xs[((rg << 3) + i) * 128 + k];
            acc[i][0] = fmaf(xv, w.x, acc[i][0]);
            acc[i][1] = fmaf(xv, w.y, acc[i][1]);
            acc[i][2] = fmaf(xv, w.z, acc[i][2]);
            acc[i][3] = fmaf(xv, w.w, acc[i][3]);
        }
    }

    float4* H4 = (float4*)Hout;
#pragma unroll
    for (int i = 0; i < 8; i++) {
        int r = rbase + (rg << 3) + i;
        if (r < NN)
            H4[r * 32 + colg] = make_float4(acc[i][0], acc[i][1], acc[i][2], acc[i][3]);
    }
}

// ---------------- per-node attention scalars: as[n,h], ad[n,h] ----------------
template <int H>
__global__ void k_attn(const float* __restrict__ Hf, const float* __restrict__ asrc,
                       const float* __restrict__ adst, float* __restrict__ As,
                       float* __restrict__ Ad) {
    int warp = (blockIdx.x * blockDim.x + threadIdx.x) >> 5;
    int lane = threadIdx.x & 31;
    if (warp >= NN) return;
    float4 h = ((const float4*)Hf)[warp * 32 + lane];
    float4 s4 = ((const float4*)asrc)[lane];
    float4 d4 = ((const float4*)adst)[lane];
    float ps = h.x * s4.x + h.y * s4.y + h.z * s4.z + h.w * s4.w;
    float pd = h.x * d4.x + h.y * d4.y + h.z * d4.z + h.w * d4.w;
    if (H == 4) {
#pragma unroll
        for (int o = 4; o >= 1; o >>= 1) {
            ps += __shfl_xor_sync(0xffffffffu, ps, o);
            pd += __shfl_xor_sync(0xffffffffu, pd, o);
        }
        if ((lane & 7) == 0) {
            As[warp * 4 + (lane >> 3)] = ps;
            Ad[warp * 4 + (lane >> 3)] = pd;
        }
    } else {
#pragma unroll
        for (int o = 16; o >= 1; o >>= 1) {
            ps += __shfl_xor_sync(0xffffffffu, ps, o);
            pd += __shfl_xor_sync(0xffffffffu, pd, o);
        }
        if (lane == 0) { As[warp] = ps; Ad[warp] = pd; }
    }
}

// ---------------- warp-per-node online-softmax aggregation ----------------
template <int H, bool ELU>
__global__ void k_agg(const float* __restrict__ Hf, const float* __restrict__ As,
                      const float* __restrict__ Ad, const float* __restrict__ bias,
                      float* __restrict__ out) {
    int warp = (blockIdx.x * blockDim.x + threadIdx.x) >> 5;
    int lane = threadIdx.x & 31;
    if (warp >= NN) return;
    int head = (H == 4) ? (lane >> 3) : 0;
    int e0 = g_off[warp], e1 = g_off[warp + 1];
    float adv = Ad[warp * H + head];

    float m = -1e30f, den = 0.f;
    float4 acc = make_float4(0.f, 0.f, 0.f, 0.f);
    const float4* H4 = (const float4*)Hf;

    for (int e = e0; e < e1; e++) {
        int s = g_csr[e];
        float a = As[s * H + head];
        float logit = a + adv;
        logit = (logit > 0.f) ? logit : SLOPE * logit;
        float nm = fmaxf(m, logit);
        float r = __expf(m - nm);
        float w = __expf(logit - nm);
        float4 hv = H4[s * 32 + lane];
        acc.x = acc.x * r + w * hv.x;
        acc.y = acc.y * r + w * hv.y;
        acc.z = acc.z * r + w * hv.z;
        acc.w = acc.w * r + w * hv.w;
        den = den * r + w;
        m = nm;
    }
    float inv = 1.f / den;
    float4 b = ((const float4*)bias)[lane];
    float4 o;
    o.x = acc.x * inv + b.x;
    o.y = acc.y * inv + b.y;
    o.z = acc.z * inv + b.z;
    o.w = acc.w * inv + b.w;
    if (ELU) {
        o.x = (o.x > 0.f) ? o.x : expm1f(o.x);
        o.y = (o.y > 0.f) ? o.y : expm1f(o.y);
        o.z = (o.z > 0.f) ? o.z : expm1f(o.z);
        o.w = (o.w > 0.f) ? o.w : expm1f(o.w);
    }
    ((float4*)out)[warp * 32 + lane] = o;
}

// ---------------- host launcher ----------------
extern "C" void kernel_launch(void* const* d_in, const int* in_sizes, int n_in,
                              void* d_out, int out_size) {
    const float* x   = (const float*)d_in[0];
    const int*   ei  = (const int*)d_in[1];
    const float* W1  = (const float*)d_in[2];
    const float* as1 = (const float*)d_in[3];
    const float* ad1 = (const float*)d_in[4];
    const float* b1  = (const float*)d_in[5];
    const float* W2  = (const float*)d_in[6];
    const float* as2 = (const float*)d_in[7];
    const float* ad2 = (const float*)d_in[8];
    const float* b2  = (const float*)d_in[9];
    const float* W3  = (const float*)d_in[10];
    const float* as3 = (const float*)d_in[11];
    const float* ad3 = (const float*)d_in[12];
    const float* b3  = (const float*)d_in[13];
    const int* src = ei;
    const int* dst = ei + EE;

    const int smem_gemm = (16384 + 8192) * 4;  // 96 KB
    cudaFuncSetAttribute(k_gemm, cudaFuncAttributeMaxDynamicSharedMemorySize, smem_gemm);

    float* d_h    = nullptr;
    float* d_feat = nullptr;
    float* d_As   = nullptr;
    float* d_Ad   = nullptr;
    cudaGetSymbolAddress((void**)&d_h, g_h);
    cudaGetSymbolAddress((void**)&d_feat, g_feat);
    cudaGetSymbolAddress((void**)&d_As, g_as);
    cudaGetSymbolAddress((void**)&d_Ad, g_ad);

    // ---- CSR build (by dst) ----
    k_init<<<(NN + 255) / 256, 256>>>();
    k_count<<<(EE + 255) / 256, 256>>>(dst);
    k_scan<<<1, 1024>>>();
    k_scatter<<<(ET + 255) / 256, 256>>>(src, dst);

    const int gemm_blocks = (NN + 63) / 64;
    const int node_warp_blocks = (NN * 32 + 255) / 256;  // warp per node

    // ---- layer 1: x -> feat ----
    k_gemm<<<gemm_blocks, 256, smem_gemm>>>(x, W1, d_h);
    k_attn<4><<<node_warp_blocks, 256>>>(d_h, as1, ad1, d_As, d_Ad);
    k_agg<4, true><<<node_warp_blocks, 256>>>(d_h, d_As, d_Ad, b1, d_feat);

    // ---- layer 2: feat -> feat ----
    k_gemm<<<gemm_blocks, 256, smem_gemm>>>(d_feat, W2, d_h);
    k_attn<4><<<node_warp_blocks, 256>>>(d_h, as2, ad2, d_As, d_Ad);
    k_agg<4, true><<<node_warp_blocks, 256>>>(d_h, d_As, d_Ad, b2, d_feat);

    // ---- layer 3: feat -> out (heads=1, no ELU) ----
    k_gemm<<<gemm_blocks, 256, smem_gemm>>>(d_feat, W3, d_h);
    k_attn<1><<<node_warp_blocks, 256>>>(d_h, as3, ad3, d_As, d_Ad);
    k_agg<1, false><<<node_warp_blocks, 256>>>(d_h, d_As, d_Ad, b3, (float*)d_out);
}

// round 6
// speedup vs baseline: 1.4069x; 1.4069x over previous
#include <cuda_runtime.h>
#include <math.h>

#define NN 100000
#define EE 1600000
#define ET (EE + NN)
#define SLOPE 0.2f

// ---------------- scratch (static device globals; no runtime allocation) ----------------
__device__ __align__(16) float g_h[NN * 128];     // transformed features (x @ W)
__device__ __align__(16) float g_feat[NN * 128];  // layer activations (post bias+ELU)
__device__ __align__(16) float g_as[NN * 4];      // per-node attention src scalar (per head)
__device__ __align__(16) float g_ad[NN * 4];      // per-node attention dst scalar (per head)
__device__ int g_off[NN + 1];                     // CSR offsets (by dst)
__device__ int g_cur[NN];                         // scatter cursors
__device__ int g_csr[ET];                         // CSR: src index per incoming edge

// ---------------- CSR build ----------------
__global__ void k_init() {
    int i = blockIdx.x * blockDim.x + threadIdx.x;
    if (i < NN) g_off[i] = 1;  // self loop
}

__global__ void k_count(const int* __restrict__ dst) {
    int i = blockIdx.x * blockDim.x + threadIdx.x;
    if (i < EE) atomicAdd(&g_off[dst[i]], 1);
}

// single-block exclusive scan over g_off[0..NN-1], in place; writes g_cur too.
__global__ void k_scan() {
    __shared__ int swarp[32];
    __shared__ int s_carry;
    int t = threadIdx.x, lane = t & 31, wid = t >> 5;
    if (t == 0) s_carry = 0;
    __syncthreads();
    for (int base = 0; base < NN; base += 1024) {
        int i = base + t;
        int v = (i < NN) ? g_off[i] : 0;
        int c = s_carry;
        int x = v;
#pragma unroll
        for (int o = 1; o < 32; o <<= 1) {
            int y = __shfl_up_sync(0xffffffffu, x, o);
            if (lane >= o) x += y;
        }
        if (lane == 31) swarp[wid] = x;
        __syncthreads();
        if (wid == 0) {
            int y = swarp[lane];
#pragma unroll
            for (int o = 1; o < 32; o <<= 1) {
                int z = __shfl_up_sync(0xffffffffu, y, o);
                if (lane >= o) y += z;
            }
            swarp[lane] = y;
        }
        __syncthreads();
        int incl = x + ((wid > 0) ? swarp[wid - 1] : 0) + c;
        int excl = incl - v;
        if (i < NN) { g_off[i] = excl; g_cur[i] = excl; }
        __syncthreads();
        if (t == 0) s_carry = c + swarp[31];
        __syncthreads();
    }
    if (threadIdx.x == 0) g_off[NN] = s_carry;  // = ET
}

__global__ void k_scatter(const int* __restrict__ src, const int* __restrict__ dst) {
    int i = blockIdx.x * blockDim.x + threadIdx.x;
    if (i < ET) {
        int s, d;
        if (i < EE) { s = src[i]; d = dst[i]; }
        else        { s = i - EE; d = s; }
        int pos = atomicAdd(&g_cur[d], 1);
        g_csr[pos] = s;
    }
}

// ---------------- fused GEMM + attention scalars ----------------
// H[n,128] = X[n,128] @ W[128,128]; As/Ad[n,h] = <H[n], att_src/att_dst>
// W fully resident in SMEM (64KB) + 64-row X tile (32KB). 256 threads.
// Warp w holds rows rbase + w*8 .. +7 completely (lane = colg owns channels colg*4..+3).
template <int H>
__global__ void __launch_bounds__(256, 2) k_gemm(
        const float* __restrict__ X, const float* __restrict__ W,
        const float* __restrict__ asrc, const float* __restrict__ adst,
        float* __restrict__ Hout, float* __restrict__ As, float* __restrict__ Ad) {
    extern __shared__ float sm[];
    float* Ws = sm;            // 16384 floats
    float* Xs = sm + 16384;    // 8192 floats
    int t = threadIdx.x;
    int rbase = blockIdx.x * 64;

    const float4* W4 = (const float4*)W;
    float4* Ws4 = (float4*)Ws;
#pragma unroll
    for (int i = 0; i < 16; i++) Ws4[t + i * 256] = W4[t + i * 256];

    const float4* X4 = (const float4*)X;
    float4* Xs4 = (float4*)Xs;
#pragma unroll
    for (int i = 0; i < 8; i++) {
        int idx = t + i * 256;           // float4 idx in tile; row=idx>>5, col4=idx&31
        int r = rbase + (idx >> 5);
        float4 v = make_float4(0.f, 0.f, 0.f, 0.f);
        if (r < NN) v = X4[r * 32 + (idx & 31)];
        Xs4[idx] = v;
    }
    __syncthreads();

    int colg = t & 31;   // = lane
    int rg = t >> 5;     // = warp in block
    float acc[8][4];
#pragma unroll
    for (int i = 0; i < 8; i++)
#pragma unroll
        for (int j = 0; j < 4; j++) acc[i][j] = 0.f;

    const float4* XsC = (const float4*)Xs;
#pragma unroll 2
    for (int k4 = 0; k4 < 32; k4++) {
        float4 xv[8];
#pragma unroll
        for (int i = 0; i < 8; i++) xv[i] = XsC[((rg << 3) + i) * 32 + k4];
#pragma unroll
        for (int kk = 0; kk < 4; kk++) {
            float4 w = Ws4[(k4 * 4 + kk) * 32 + colg];
#pragma unroll
            for (int i = 0; i < 8; i++) {
                float xe = ((const float*)&xv[i])[kk];
                acc[i][0] = fmaf(xe, w.x, acc[i][0]);
                acc[i][1] = fmaf(xe, w.y, acc[i][1]);
                acc[i][2] = fmaf(xe, w.z, acc[i][2]);
                acc[i][3] = fmaf(xe, w.w, acc[i][3]);
            }
        }
    }

    // stores + fused attention-scalar epilogue
    float4 sv = ((const float4*)asrc)[colg];   // att vecs are flat [H*C] = 128 floats
    float4 dv = ((const float4*)adst)[colg];
    float4* H4 = (float4*)Hout;
#pragma unroll
    for (int i = 0; i < 8; i++) {
        int r = rbase + (rg << 3) + i;
        float ps = acc[i][0] * sv.x + acc[i][1] * sv.y + acc[i][2] * sv.z + acc[i][3] * sv.w;
        float pd = acc[i][0] * dv.x + acc[i][1] * dv.y + acc[i][2] * dv.z + acc[i][3] * dv.w;
        if (H == 4) {
#pragma unroll
            for (int o = 4; o >= 1; o >>= 1) {
                ps += __shfl_xor_sync(0xffffffffu, ps, o);
                pd += __shfl_xor_sync(0xffffffffu, pd, o);
            }
        } else {
#pragma unroll
            for (int o = 16; o >= 1; o >>= 1) {
                ps += __shfl_xor_sync(0xffffffffu, ps, o);
                pd += __shfl_xor_sync(0xffffffffu, pd, o);
            }
        }
        if (r < NN) {
            H4[r * 32 + colg] = make_float4(acc[i][0], acc[i][1], acc[i][2], acc[i][3]);
            if (H == 4) {
                if ((colg & 7) == 0) {
                    As[r * 4 + (colg >> 3)] = ps;
                    Ad[r * 4 + (colg >> 3)] = pd;
                }
            } else {
                if (colg == 0) { As[r] = ps; Ad[r] = pd; }
            }
        }
    }
}

// ---------------- warp-per-node 3-pass softmax aggregation ----------------
template <int H, bool ELU>
__global__ void k_agg(const float* __restrict__ Hf, const float* __restrict__ As,
                      const float* __restrict__ Ad, const float* __restrict__ bias,
                      float* __restrict__ out) {
    int warp = (blockIdx.x * blockDim.x + threadIdx.x) >> 5;
    int lane = threadIdx.x & 31;
    if (warp >= NN) return;
    int head = (H == 4) ? (lane >> 3) : 0;
    int e0 = g_off[warp], e1 = g_off[warp + 1];
    float adv = Ad[warp * H + head];
    const float4* H4 = (const float4*)Hf;

    // ---- pass 1: max logit (cheap: scalar As loads only) ----
    float m = -1e30f;
#pragma unroll 4
    for (int e = e0; e < e1; e++) {
        int s = g_csr[e];
        float a = As[s * H + head] + adv;
        a = (a > 0.f) ? a : SLOPE * a;
        m = fmaxf(m, a);
    }

    // ---- pass 2: denominator (independent exps, FADD chain only) ----
    float den = 0.f;
#pragma unroll 4
    for (int e = e0; e < e1; e++) {
        int s = g_csr[e];
        float a = As[s * H + head] + adv;
        a = (a > 0.f) ? a : SLOPE * a;
        den += __expf(a - m);
    }
    float inv = 1.f / den;

    // ---- pass 3: weighted gather-accumulate, 4 gathers in flight ----
    float4 acc = make_float4(0.f, 0.f, 0.f, 0.f);
    int e = e0;
    for (; e + 4 <= e1; e += 4) {
        int s0 = g_csr[e], s1 = g_csr[e + 1], s2 = g_csr[e + 2], s3 = g_csr[e + 3];
        float a0 = As[s0 * H + head] + adv;
        float a1 = As[s1 * H + head] + adv;
        float a2 = As[s2 * H + head] + adv;
        float a3 = As[s3 * H + head] + adv;
        float4 h0 = H4[s0 * 32 + lane];
        float4 h1 = H4[s1 * 32 + lane];
        float4 h2 = H4[s2 * 32 + lane];
        float4 h3 = H4[s3 * 32 + lane];
        a0 = (a0 > 0.f) ? a0 : SLOPE * a0;
        a1 = (a1 > 0.f) ? a1 : SLOPE * a1;
        a2 = (a2 > 0.f) ? a2 : SLOPE * a2;
        a3 = (a3 > 0.f) ? a3 : SLOPE * a3;
        float w0 = __expf(a0 - m), w1 = __expf(a1 - m);
        float w2 = __expf(a2 - m), w3 = __expf(a3 - m);
        acc.x = fmaf(w0, h0.x, acc.x); acc.y = fmaf(w0, h0.y, acc.y);
        acc.z = fmaf(w0, h0.z, acc.z); acc.w = fmaf(w0, h0.w, acc.w);
        acc.x = fmaf(w1, h1.x, acc.x); acc.y = fmaf(w1, h1.y, acc.y);
        acc.z = fmaf(w1, h1.z, acc.z); acc.w = fmaf(w1, h1.w, acc.w);
        acc.x = fmaf(w2, h2.x, acc.x); acc.y = fmaf(w2, h2.y, acc.y);
        acc.z = fmaf(w2, h2.z, acc.z); acc.w = fmaf(w2, h2.w, acc.w);
        acc.x = fmaf(w3, h3.x, acc.x); acc.y = fmaf(w3, h3.y, acc.y);
        acc.z = fmaf(w3, h3.z, acc.z); acc.w = fmaf(w3, h3.w, acc.w);
    }
    for (; e < e1; e++) {
        int s = g_csr[e];
        float a = As[s * H + head] + adv;
        a = (a > 0.f) ? a : SLOPE * a;
        float w = __expf(a - m);
        float4 hv = H4[s * 32 + lane];
        acc.x = fmaf(w, hv.x, acc.x); acc.y = fmaf(w, hv.y, acc.y);
        acc.z = fmaf(w, hv.z, acc.z); acc.w = fmaf(w, hv.w, acc.w);
    }

    float4 b = ((const float4*)bias)[lane];
    float4 o;
    o.x = acc.x * inv + b.x;
    o.y = acc.y * inv + b.y;
    o.z = acc.z * inv + b.z;
    o.w = acc.w * inv + b.w;
    if (ELU) {
        o.x = (o.x > 0.f) ? o.x : expm1f(o.x);
        o.y = (o.y > 0.f) ? o.y : expm1f(o.y);
        o.z = (o.z > 0.f) ? o.z : expm1f(o.z);
        o.w = (o.w > 0.f) ? o.w : expm1f(o.w);
    }
    ((float4*)out)[warp * 32 + lane] = o;
}

// ---------------- host launcher ----------------
extern "C" void kernel_launch(void* const* d_in, const int* in_sizes, int n_in,
                              void* d_out, int out_size) {
    const float* x   = (const float*)d_in[0];
    const int*   ei  = (const int*)d_in[1];
    const float* W1  = (const float*)d_in[2];
    const float* as1 = (const float*)d_in[3];
    const float* ad1 = (const float*)d_in[4];
    const float* b1  = (const float*)d_in[5];
    const float* W2  = (const float*)d_in[6];
    const float* as2 = (const float*)d_in[7];
    const float* ad2 = (const float*)d_in[8];
    const float* b2  = (const float*)d_in[9];
    const float* W3  = (const float*)d_in[10];
    const float* as3 = (const float*)d_in[11];
    const float* ad3 = (const float*)d_in[12];
    const float* b3  = (const float*)d_in[13];
    const int* src = ei;
    const int* dst = ei + EE;

    const int smem_gemm = (16384 + 8192) * 4;  // 96 KB
    cudaFuncSetAttribute(k_gemm<4>, cudaFuncAttributeMaxDynamicSharedMemorySize, smem_gemm);
    cudaFuncSetAttribute(k_gemm<1>, cudaFuncAttributeMaxDynamicSharedMemorySize, smem_gemm);

    float* d_h    = nullptr;
    float* d_feat = nullptr;
    float* d_As   = nullptr;
    float* d_Ad   = nullptr;
    cudaGetSymbolAddress((void**)&d_h, g_h);
    cudaGetSymbolAddress((void**)&d_feat, g_feat);
    cudaGetSymbolAddress((void**)&d_As, g_as);
    cudaGetSymbolAddress((void**)&d_Ad, g_ad);

    // ---- CSR build (by dst) ----
    k_init<<<(NN + 255) / 256, 256>>>();
    k_count<<<(EE + 255) / 256, 256>>>(dst);
    k_scan<<<1, 1024>>>();
    k_scatter<<<(ET + 255) / 256, 256>>>(src, dst);

    const int gemm_blocks = (NN + 63) / 64;
    const int node_warp_blocks = (NN * 32 + 255) / 256;  // warp per node

    // ---- layer 1: x -> feat ----
    k_gemm<4><<<gemm_blocks, 256, smem_gemm>>>(x, W1, as1, ad1, d_h, d_As, d_Ad);
    k_agg<4, true><<<node_warp_blocks, 256>>>(d_h, d_As, d_Ad, b1, d_feat);

    // ---- layer 2: feat -> feat ----
    k_gemm<4><<<gemm_blocks, 256, smem_gemm>>>(d_feat, W2, as2, ad2, d_h, d_As, d_Ad);
    k_agg<4, true><<<node_warp_blocks, 256>>>(d_h, d_As, d_Ad, b2, d_feat);

    // ---- layer 3: feat -> out (heads=1, no ELU) ----
    k_gemm<1><<<gemm_blocks, 256, smem_gemm>>>(d_feat, W3, as3, ad3, d_h, d_As, d_Ad);
    k_agg<1, false><<<node_warp_blocks, 256>>>(d_h, d_As, d_Ad, b3, (float*)d_out);
}

// round 7
// speedup vs baseline: 1.4799x; 1.0519x over previous
#include <cuda_runtime.h>
#include <math.h>

#define NN 100000
#define EE 1600000
#define ET (EE + NN)
#define SLOPE 0.2f

// ---------------- scratch (static device globals; no runtime allocation) ----------------
__device__ __align__(16) float g_h[NN * 128];     // transformed features (x @ W)
__device__ __align__(16) float g_feat[NN * 128];  // layer activations (post bias+ELU)
__device__ __align__(16) float g_as[NN * 4];      // per-node attention src scalar (per head)
__device__ __align__(16) float g_ad[NN * 4];      // per-node attention dst scalar (per head)
__device__ int g_off[NN + 1];                     // CSR offsets (by dst)
__device__ int g_cur[NN];                         // scatter cursors
__device__ int g_csr[ET];                         // CSR: src index per incoming edge

// ---------------- CSR build ----------------
__global__ void k_init() {
    int i = blockIdx.x * blockDim.x + threadIdx.x;
    if (i < NN) g_off[i] = 1;  // self loop
}

__global__ void k_count(const int* __restrict__ dst) {
    int i = blockIdx.x * blockDim.x + threadIdx.x;
    if (i < EE) atomicAdd(&g_off[dst[i]], 1);
}

// single-block exclusive scan over g_off[0..NN-1], in place; writes g_cur too.
__global__ void k_scan() {
    __shared__ int swarp[32];
    __shared__ int s_carry;
    int t = threadIdx.x, lane = t & 31, wid = t >> 5;
    if (t == 0) s_carry = 0;
    __syncthreads();
    for (int base = 0; base < NN; base += 1024) {
        int i = base + t;
        int v = (i < NN) ? g_off[i] : 0;
        int c = s_carry;
        int x = v;
#pragma unroll
        for (int o = 1; o < 32; o <<= 1) {
            int y = __shfl_up_sync(0xffffffffu, x, o);
            if (lane >= o) x += y;
        }
        if (lane == 31) swarp[wid] = x;
        __syncthreads();
        if (wid == 0) {
            int y = swarp[lane];
#pragma unroll
            for (int o = 1; o < 32; o <<= 1) {
                int z = __shfl_up_sync(0xffffffffu, y, o);
                if (lane >= o) y += z;
            }
            swarp[lane] = y;
        }
        __syncthreads();
        int incl = x + ((wid > 0) ? swarp[wid - 1] : 0) + c;
        int excl = incl - v;
        if (i < NN) { g_off[i] = excl; g_cur[i] = excl; }
        __syncthreads();
        if (t == 0) s_carry = c + swarp[31];
        __syncthreads();
    }
    if (threadIdx.x == 0) g_off[NN] = s_carry;  // = ET
}

__global__ void k_scatter(const int* __restrict__ src, const int* __restrict__ dst) {
    int i = blockIdx.x * blockDim.x + threadIdx.x;
    if (i < ET) {
        int s, d;
        if (i < EE) { s = src[i]; d = dst[i]; }
        else        { s = i - EE; d = s; }
        int pos = atomicAdd(&g_cur[d], 1);
        g_csr[pos] = s;
    }
}

// ---------------- fused GEMM + attention scalars ----------------
// H[n,128] = X[n,128] @ W[128,128]; As/Ad[n,h] = <H[n], att_src/att_dst>
// W fully resident in SMEM (64KB) + 64-row X tile (32KB). 256 threads.
// Warp w holds rows rbase + w*8 .. +7 completely (lane = colg owns channels colg*4..+3).
template <int H>
__global__ void __launch_bounds__(256, 2) k_gemm(
        const float* __restrict__ X, const float* __restrict__ W,
        const float* __restrict__ asrc, const float* __restrict__ adst,
        float* __restrict__ Hout, float* __restrict__ As, float* __restrict__ Ad) {
    extern __shared__ float sm[];
    float* Ws = sm;            // 16384 floats
    float* Xs = sm + 16384;    // 8192 floats
    int t = threadIdx.x;
    int rbase = blockIdx.x * 64;

    const float4* W4 = (const float4*)W;
    float4* Ws4 = (float4*)Ws;
#pragma unroll
    for (int i = 0; i < 16; i++) Ws4[t + i * 256] = W4[t + i * 256];

    const float4* X4 = (const float4*)X;
    float4* Xs4 = (float4*)Xs;
#pragma unroll
    for (int i = 0; i < 8; i++) {
        int idx = t + i * 256;           // float4 idx in tile; row=idx>>5, col4=idx&31
        int r = rbase + (idx >> 5);
        float4 v = make_float4(0.f, 0.f, 0.f, 0.f);
        if (r < NN) v = X4[r * 32 + (idx & 31)];
        Xs4[idx] = v;
    }
    __syncthreads();

    int colg = t & 31;   // = lane
    int rg = t >> 5;     // = warp in block
    float acc[8][4];
#pragma unroll
    for (int i = 0; i < 8; i++)
#pragma unroll
        for (int j = 0; j < 4; j++) acc[i][j] = 0.f;

    const float4* XsC = (const float4*)Xs;
#pragma unroll 2
    for (int k4 = 0; k4 < 32; k4++) {
        float4 xv[8];
#pragma unroll
        for (int i = 0; i < 8; i++) xv[i] = XsC[((rg << 3) + i) * 32 + k4];
#pragma unroll
        for (int kk = 0; kk < 4; kk++) {
            float4 w = Ws4[(k4 * 4 + kk) * 32 + colg];
#pragma unroll
            for (int i = 0; i < 8; i++) {
                float xe = ((const float*)&xv[i])[kk];
                acc[i][0] = fmaf(xe, w.x, acc[i][0]);
                acc[i][1] = fmaf(xe, w.y, acc[i][1]);
                acc[i][2] = fmaf(xe, w.z, acc[i][2]);
                acc[i][3] = fmaf(xe, w.w, acc[i][3]);
            }
        }
    }

    // stores + fused attention-scalar epilogue
    float4 sv = ((const float4*)asrc)[colg];   // att vecs are flat [H*C] = 128 floats
    float4 dv = ((const float4*)adst)[colg];
    float4* H4 = (float4*)Hout;
#pragma unroll
    for (int i = 0; i < 8; i++) {
        int r = rbase + (rg << 3) + i;
        float ps = acc[i][0] * sv.x + acc[i][1] * sv.y + acc[i][2] * sv.z + acc[i][3] * sv.w;
        float pd = acc[i][0] * dv.x + acc[i][1] * dv.y + acc[i][2] * dv.z + acc[i][3] * dv.w;
        if (H == 4) {
#pragma unroll
            for (int o = 4; o >= 1; o >>= 1) {
                ps += __shfl_xor_sync(0xffffffffu, ps, o);
                pd += __shfl_xor_sync(0xffffffffu, pd, o);
            }
        } else {
#pragma unroll
            for (int o = 16; o >= 1; o >>= 1) {
                ps += __shfl_xor_sync(0xffffffffu, ps, o);
                pd += __shfl_xor_sync(0xffffffffu, pd, o);
            }
        }
        if (r < NN) {
            H4[r * 32 + colg] = make_float4(acc[i][0], acc[i][1], acc[i][2], acc[i][3]);
            if (H == 4) {
                if ((colg & 7) == 0) {
                    As[r * 4 + (colg >> 3)] = ps;
                    Ad[r * 4 + (colg >> 3)] = pd;
                }
            } else {
                if (colg == 0) { As[r] = ps; Ad[r] = pd; }
            }
        }
    }
}

// ---------------- warp-per-node 2-pass softmax aggregation ----------------
// pass 1: max over logits (scalar loads only, no exp)
// pass 2: fused gather + exp + accumulate (den accumulated alongside, applied once)
template <int H, bool ELU>
__global__ void k_agg(const float* __restrict__ Hf, const float* __restrict__ As,
                      const float* __restrict__ Ad, const float* __restrict__ bias,
                      float* __restrict__ out) {
    int warp = (blockIdx.x * blockDim.x + threadIdx.x) >> 5;
    int lane = threadIdx.x & 31;
    if (warp >= NN) return;
    int head = (H == 4) ? (lane >> 3) : 0;
    int e0 = g_off[warp], e1 = g_off[warp + 1];
    float adv = Ad[warp * H + head];
    const float4* H4 = (const float4*)Hf;

    // ---- pass 1: max logit (scalar As loads; L1/L2-resident) ----
    float m = -1e30f;
#pragma unroll 4
    for (int e = e0; e < e1; e++) {
        int s = g_csr[e];
        float a = As[s * H + head] + adv;
        a = (a > 0.f) ? a : SLOPE * a;
        m = fmaxf(m, a);
    }

    // ---- pass 2: gather + exp + accumulate (8 gathers in flight) ----
    float den = 0.f;
    float4 acc = make_float4(0.f, 0.f, 0.f, 0.f);
    int e = e0;
    for (; e + 8 <= e1; e += 8) {
        int s[8];
        float a[8];
        float4 hv[8];
#pragma unroll
        for (int j = 0; j < 8; j++) s[j] = g_csr[e + j];
#pragma unroll
        for (int j = 0; j < 8; j++) hv[j] = H4[s[j] * 32 + lane];
#pragma unroll
        for (int j = 0; j < 8; j++) a[j] = As[s[j] * H + head] + adv;
#pragma unroll
        for (int j = 0; j < 8; j++) {
            float l = a[j];
            l = (l > 0.f) ? l : SLOPE * l;
            float w = __expf(l - m);
            den += w;
            acc.x = fmaf(w, hv[j].x, acc.x);
            acc.y = fmaf(w, hv[j].y, acc.y);
            acc.z = fmaf(w, hv[j].z, acc.z);
            acc.w = fmaf(w, hv[j].w, acc.w);
        }
    }
    for (; e < e1; e++) {
        int s = g_csr[e];
        float a = As[s * H + head] + adv;
        a = (a > 0.f) ? a : SLOPE * a;
        float w = __expf(a - m);
        float4 hv = H4[s * 32 + lane];
        den += w;
        acc.x = fmaf(w, hv.x, acc.x);
        acc.y = fmaf(w, hv.y, acc.y);
        acc.z = fmaf(w, hv.z, acc.z);
        acc.w = fmaf(w, hv.w, acc.w);
    }

    float inv = 1.f / den;
    float4 b = ((const float4*)bias)[lane];
    float4 o;
    o.x = acc.x * inv + b.x;
    o.y = acc.y * inv + b.y;
    o.z = acc.z * inv + b.z;
    o.w = acc.w * inv + b.w;
    if (ELU) {
        o.x = (o.x > 0.f) ? o.x : expm1f(o.x);
        o.y = (o.y > 0.f) ? o.y : expm1f(o.y);
        o.z = (o.z > 0.f) ? o.z : expm1f(o.z);
        o.w = (o.w > 0.f) ? o.w : expm1f(o.w);
    }
    ((float4*)out)[warp * 32 + lane] = o;
}

// ---------------- host launcher ----------------
extern "C" void kernel_launch(void* const* d_in, const int* in_sizes, int n_in,
                              void* d_out, int out_size) {
    const float* x   = (const float*)d_in[0];
    const int*   ei  = (const int*)d_in[1];
    const float* W1  = (const float*)d_in[2];
    const float* as1 = (const float*)d_in[3];
    const float* ad1 = (const float*)d_in[4];
    const float* b1  = (const float*)d_in[5];
    const float* W2  = (const float*)d_in[6];
    const float* as2 = (const float*)d_in[7];
    const float* ad2 = (const float*)d_in[8];
    const float* b2  = (const float*)d_in[9];
    const float* W3  = (const float*)d_in[10];
    const float* as3 = (const float*)d_in[11];
    const float* ad3 = (const float*)d_in[12];
    const float* b3  = (const float*)d_in[13];
    const int* src = ei;
    const int* dst = ei + EE;

    const int smem_gemm = (16384 + 8192) * 4;  // 96 KB
    cudaFuncSetAttribute(k_gemm<4>, cudaFuncAttributeMaxDynamicSharedMemorySize, smem_gemm);
    cudaFuncSetAttribute(k_gemm<1>, cudaFuncAttributeMaxDynamicSharedMemorySize, smem_gemm);

    float* d_h    = nullptr;
    float* d_feat = nullptr;
    float* d_As   = nullptr;
    float* d_Ad   = nullptr;
    cudaGetSymbolAddress((void**)&d_h, g_h);
    cudaGetSymbolAddress((void**)&d_feat, g_feat);
    cudaGetSymbolAddress((void**)&d_As, g_as);
    cudaGetSymbolAddress((void**)&d_Ad, g_ad);

    // ---- CSR build (by dst) ----
    k_init<<<(NN + 255) / 256, 256>>>();
    k_count<<<(EE + 255) / 256, 256>>>(dst);
    k_scan<<<1, 1024>>>();
    k_scatter<<<(ET + 255) / 256, 256>>>(src, dst);

    const int gemm_blocks = (NN + 63) / 64;
    const int node_warp_blocks = (NN * 32 + 255) / 256;  // warp per node

    // ---- layer 1: x -> feat ----
    k_gemm<4><<<gemm_blocks, 256, smem_gemm>>>(x, W1, as1, ad1, d_h, d_As, d_Ad);
    k_agg<4, true><<<node_warp_blocks, 256>>>(d_h, d_As, d_Ad, b1, d_feat);

    // ---- layer 2: feat -> feat ----
    k_gemm<4><<<gemm_blocks, 256, smem_gemm>>>(d_feat, W2, as2, ad2, d_h, d_As, d_Ad);
    k_agg<4, true><<<node_warp_blocks, 256>>>(d_h, d_As, d_Ad, b2, d_feat);

    // ---- layer 3: feat -> out (heads=1, no ELU) ----
    k_gemm<1><<<gemm_blocks, 256, smem_gemm>>>(d_feat, W3, as3, ad3, d_h, d_As, d_Ad);
    k_agg<1, false><<<node_warp_blocks, 256>>>(d_h, d_As, d_Ad, b3, (float*)d_out);
}

// round 8
// speedup vs baseline: 1.6056x; 1.0850x over previous
#include <cuda_runtime.h>
#include <math.h>
#include <stdint.h>

#define NN 100000
#define EE 1600000
#define ET (EE + NN)
#define SLOPE 0.2f

// ---------------- scratch (static device globals; no runtime allocation) ----------------
__device__ __align__(16) float g_h[NN * 128];     // transformed features (x @ W)
__device__ __align__(16) float g_feat[NN * 128];  // layer activations (post bias+ELU)
__device__ __align__(16) float g_as[NN * 4];      // per-node attention src scalar (per head)
__device__ __align__(16) float g_ad[NN * 4];      // per-node attention dst scalar (per head)
__device__ int g_off[NN + 1];                     // CSR offsets (by dst)
__device__ int g_cur[NN];                         // scatter cursors
__device__ int g_csr[ET];                         // CSR: src index per incoming edge

// ---------------- CSR build ----------------
__global__ void k_init() {
    int i = blockIdx.x * blockDim.x + threadIdx.x;
    if (i < NN) g_off[i] = 1;  // self loop
}

__global__ void k_count(const int* __restrict__ dst) {
    int i = blockIdx.x * blockDim.x + threadIdx.x;
    if (i < EE) atomicAdd(&g_off[dst[i]], 1);
}

// single-block exclusive scan over g_off[0..NN-1], in place; writes g_cur too.
__global__ void k_scan() {
    __shared__ int swarp[32];
    __shared__ int s_carry;
    int t = threadIdx.x, lane = t & 31, wid = t >> 5;
    if (t == 0) s_carry = 0;
    __syncthreads();
    for (int base = 0; base < NN; base += 1024) {
        int i = base + t;
        int v = (i < NN) ? g_off[i] : 0;
        int c = s_carry;
        int x = v;
#pragma unroll
        for (int o = 1; o < 32; o <<= 1) {
            int y = __shfl_up_sync(0xffffffffu, x, o);
            if (lane >= o) x += y;
        }
        if (lane == 31) swarp[wid] = x;
        __syncthreads();
        if (wid == 0) {
            int y = swarp[lane];
#pragma unroll
            for (int o = 1; o < 32; o <<= 1) {
                int z = __shfl_up_sync(0xffffffffu, y, o);
                if (lane >= o) y += z;
            }
            swarp[lane] = y;
        }
        __syncthreads();
        int incl = x + ((wid > 0) ? swarp[wid - 1] : 0) + c;
        int excl = incl - v;
        if (i < NN) { g_off[i] = excl; g_cur[i] = excl; }
        __syncthreads();
        if (t == 0) s_carry = c + swarp[31];
        __syncthreads();
    }
    if (threadIdx.x == 0) g_off[NN] = s_carry;  // = ET
}

__global__ void k_scatter(const int* __restrict__ src, const int* __restrict__ dst) {
    int i = blockIdx.x * blockDim.x + threadIdx.x;
    if (i < ET) {
        int s, d;
        if (i < EE) { s = src[i]; d = dst[i]; }
        else        { s = i - EE; d = s; }
        int pos = atomicAdd(&g_cur[d], 1);
        g_csr[pos] = s;
    }
}

// ---------------- tf32 helpers ----------------
__device__ __forceinline__ uint32_t f2tf(float f) {
    uint32_t u;
    asm("cvt.rna.tf32.f32 %0, %1;" : "=r"(u) : "f"(f));
    return u;
}

__device__ __forceinline__ void mma_tf32(float4& c, const uint32_t* a, uint32_t b0, uint32_t b1) {
    asm volatile(
        "mma.sync.aligned.m16n8k8.row.col.f32.tf32.tf32.f32 "
        "{%0,%1,%2,%3}, {%4,%5,%6,%7}, {%8,%9}, {%0,%1,%2,%3};\n"
        : "+f"(c.x), "+f"(c.y), "+f"(c.z), "+f"(c.w)
        : "r"(a[0]), "r"(a[1]), "r"(a[2]), "r"(a[3]), "r"(b0), "r"(b1));
}

// ---------------- tensor-core GEMM (3xTF32) + fused attention scalars ----------------
// H[n,128] = X[n,128] @ W[128,128]; As/Ad[n,h] = <H[n], att_src/att_dst>
// 128 threads = 4 warps: warp = (wm, wn), wm = M half (32 rows), wn = N half (64 cols).
// M tile = 64 rows/block. SMEM: W (swizzled, 64KB) + X tile (swizzled, 32KB) + 1KB reduce.
// Swizzles (bank-conflict-free for mma fragment LDS patterns):
//   Xs float idx: row*128 + (k ^ ((row&7)<<2))
//   Ws float idx: k*128 + (col ^ ((k&3)<<3))
template <int H>
__global__ void __launch_bounds__(128, 2) k_gemm(
        const float* __restrict__ X, const float* __restrict__ W,
        const float* __restrict__ asrc, const float* __restrict__ adst,
        float* __restrict__ Hout, float* __restrict__ As, float* __restrict__ Ad) {
    extern __shared__ float sm[];
    float* Ws = sm;              // 16384 floats
    float* Xs = sm + 16384;      // 8192 floats
    float* s_red = sm + 24576;   // 256 floats (H==1 cross-warp reduce)
    int t = threadIdx.x;
    int lane = t & 31, wid = t >> 5;
    int wm = wid >> 1, wn = wid & 1;
    int q = lane >> 2;           // 0..7
    int rr = lane & 3;           // 0..3
    int rbase = blockIdx.x * 64;

    // ---- load W (swizzled) ----
    const float4* W4 = (const float4*)W;
    float4* Ws4 = (float4*)Ws;
#pragma unroll
    for (int i = 0; i < 32; i++) {
        int idx = t + i * 128;              // 0..4095
        int k = idx >> 5, c4 = idx & 31;
        Ws4[k * 32 + (c4 ^ ((k & 3) << 1))] = W4[idx];
    }
    // ---- load X tile (swizzled, zero-padded) ----
    const float4* X4 = (const float4*)X;
    float4* Xs4 = (float4*)Xs;
#pragma unroll
    for (int i = 0; i < 16; i++) {
        int idx = t + i * 128;
        int row = idx >> 5, c4 = idx & 31;
        int r = rbase + row;
        float4 v = make_float4(0.f, 0.f, 0.f, 0.f);
        if (r < NN) v = X4[r * 32 + c4];
        Xs4[row * 32 + (c4 ^ (row & 7))] = v;
    }
    __syncthreads();

    float4 C[2][8];
#pragma unroll
    for (int mt = 0; mt < 2; mt++)
#pragma unroll
        for (int n = 0; n < 8; n++) C[mt][n] = make_float4(0.f, 0.f, 0.f, 0.f);

    int asw = q << 2;  // A swizzle: (row&7)*4 with row&7 == q
    int bsw = rr << 3; // B swizzle: (k&3)*8 with k&3 == rr

#pragma unroll 2
    for (int kc = 0; kc < 16; kc++) {
        int k0 = kc * 8 + rr;
        uint32_t Ah[2][4], Al[2][4];
#pragma unroll
        for (int mt = 0; mt < 2; mt++) {
            int r0 = wm * 32 + mt * 16 + q;
            int r1 = r0 + 8;
            float a0 = Xs[r0 * 128 + (k0 ^ asw)];
            float a1 = Xs[r1 * 128 + (k0 ^ asw)];
            float a2 = Xs[r0 * 128 + ((k0 + 4) ^ asw)];
            float a3 = Xs[r1 * 128 + ((k0 + 4) ^ asw)];
            Ah[mt][0] = f2tf(a0); Al[mt][0] = f2tf(a0 - __uint_as_float(Ah[mt][0]));
            Ah[mt][1] = f2tf(a1); Al[mt][1] = f2tf(a1 - __uint_as_float(Ah[mt][1]));
            Ah[mt][2] = f2tf(a2); Al[mt][2] = f2tf(a2 - __uint_as_float(Ah[mt][2]));
            Ah[mt][3] = f2tf(a3); Al[mt][3] = f2tf(a3 - __uint_as_float(Ah[mt][3]));
        }
#pragma unroll
        for (int n = 0; n < 8; n++) {
            int col = wn * 64 + n * 8 + q;
            float b0f = Ws[k0 * 128 + (col ^ bsw)];
            float b1f = Ws[(k0 + 4) * 128 + (col ^ bsw)];
            uint32_t b0h = f2tf(b0f), b1h = f2tf(b1f);
            uint32_t b0l = f2tf(b0f - __uint_as_float(b0h));
            uint32_t b1l = f2tf(b1f - __uint_as_float(b1h));
#pragma unroll
            for (int mt = 0; mt < 2; mt++) {
                mma_tf32(C[mt][n], Al[mt], b0h, b1h);
                mma_tf32(C[mt][n], Ah[mt], b0l, b1l);
                mma_tf32(C[mt][n], Ah[mt], b0h, b1h);
            }
        }
    }

    // ---- epilogue: store H + fused attention scalars ----
#pragma unroll
    for (int mt = 0; mt < 2; mt++) {
        int rt0 = wm * 32 + mt * 16 + q;  // tile row (0..63)
        int gr0 = rbase + rt0;
        int gr1 = gr0 + 8;

        // store H (float2 per (row, n-tile))
#pragma unroll
        for (int n = 0; n < 8; n++) {
            int col = wn * 64 + n * 8 + 2 * rr;
            if (gr0 < NN) *(float2*)&Hout[gr0 * 128 + col] = make_float2(C[mt][n].x, C[mt][n].y);
            if (gr1 < NN) *(float2*)&Hout[gr1 * 128 + col] = make_float2(C[mt][n].z, C[mt][n].w);
        }

        if (H == 4) {
            // head span: wn covers heads {2wn, 2wn+1}; n-tiles 0-3 -> first, 4-7 -> second
#pragma unroll
            for (int hh = 0; hh < 2; hh++) {
                float ps0 = 0.f, pd0 = 0.f, ps1 = 0.f, pd1 = 0.f;
#pragma unroll
                for (int j = 0; j < 4; j++) {
                    int n = hh * 4 + j;
                    int col = wn * 64 + n * 8 + 2 * rr;
                    float2 sv = *(const float2*)&asrc[col];
                    float2 dv = *(const float2*)&adst[col];
                    ps0 += C[mt][n].x * sv.x + C[mt][n].y * sv.y;
                    ps1 += C[mt][n].z * sv.x + C[mt][n].w * sv.y;
                    pd0 += C[mt][n].x * dv.x + C[mt][n].y * dv.y;
                    pd1 += C[mt][n].z * dv.x + C[mt][n].w * dv.y;
                }
#pragma unroll
                for (int o = 1; o <= 2; o <<= 1) {
                    ps0 += __shfl_xor_sync(0xffffffffu, ps0, o);
                    ps1 += __shfl_xor_sync(0xffffffffu, ps1, o);
                    pd0 += __shfl_xor_sync(0xffffffffu, pd0, o);
                    pd1 += __shfl_xor_sync(0xffffffffu, pd1, o);
                }
                if (rr == 0) {
                    int head = wn * 2 + hh;
                    if (gr0 < NN) { As[gr0 * 4 + head] = ps0; Ad[gr0 * 4 + head] = pd0; }
                    if (gr1 < NN) { As[gr1 * 4 + head] = ps1; Ad[gr1 * 4 + head] = pd1; }
                }
            }
        } else {
            // single head spans both wn warps -> SMEM partial combine
            float ps0 = 0.f, pd0 = 0.f, ps1 = 0.f, pd1 = 0.f;
#pragma unroll
            for (int n = 0; n < 8; n++) {
                int col = wn * 64 + n * 8 + 2 * rr;
                float2 sv = *(const float2*)&asrc[col];
                float2 dv = *(const float2*)&adst[col];
                ps0 += C[mt][n].x * sv.x + C[mt][n].y * sv.y;
                ps1 += C[mt][n].z * sv.x + C[mt][n].w * sv.y;
                pd0 += C[mt][n].x * dv.x + C[mt][n].y * dv.y;
                pd1 += C[mt][n].z * dv.x + C[mt][n].w * dv.y;
            }
#pragma unroll
            for (int o = 1; o <= 2; o <<= 1) {
                ps0 += __shfl_xor_sync(0xffffffffu, ps0, o);
                ps1 += __shfl_xor_sync(0xffffffffu, ps1, o);
                pd0 += __shfl_xor_sync(0xffffffffu, pd0, o);
                pd1 += __shfl_xor_sync(0xffffffffu, pd1, o);
            }
            if (rr == 0) {
                s_red[wn * 128 + rt0] = ps0;
                s_red[wn * 128 + 64 + rt0] = pd0;
                s_red[wn * 128 + rt0 + 8] = ps1;
                s_red[wn * 128 + 64 + rt0 + 8] = pd1;
            }
        }
    }

    if (H == 1) {
        __syncthreads();
        if (t < 64) {
            int r = rbase + t;
            if (r < NN) {
                As[r] = s_red[t] + s_red[128 + t];
                Ad[r] = s_red[64 + t] + s_red[192 + t];
            }
        }
    }
}

// ---------------- warp-per-node 2-pass softmax aggregation ----------------
template <int H, bool ELU>
__global__ void k_agg(const float* __restrict__ Hf, const float* __restrict__ As,
                      const float* __restrict__ Ad, const float* __restrict__ bias,
                      float* __restrict__ out) {
    int warp = (blockIdx.x * blockDim.x + threadIdx.x) >> 5;
    int lane = threadIdx.x & 31;
    if (warp >= NN) return;
    int head = (H == 4) ? (lane >> 3) : 0;
    int e0 = g_off[warp], e1 = g_off[warp + 1];
    float adv = Ad[warp * H + head];
    const float4* H4 = (const float4*)Hf;

    // ---- pass 1: max logit (scalar As loads; L1/L2-resident) ----
    float m = -1e30f;
#pragma unroll 4
    for (int e = e0; e < e1; e++) {
        int s = g_csr[e];
        float a = As[s * H + head] + adv;
        a = (a > 0.f) ? a : SLOPE * a;
        m = fmaxf(m, a);
    }

    // ---- pass 2: gather + exp + accumulate (8 gathers in flight) ----
    float den = 0.f;
    float4 acc = make_float4(0.f, 0.f, 0.f, 0.f);
    int e = e0;
    for (; e + 8 <= e1; e += 8) {
        int s[8];
        float a[8];
        float4 hv[8];
#pragma unroll
        for (int j = 0; j < 8; j++) s[j] = g_csr[e + j];
#pragma unroll
        for (int j = 0; j < 8; j++) hv[j] = H4[s[j] * 32 + lane];
#pragma unroll
        for (int j = 0; j < 8; j++) a[j] = As[s[j] * H + head] + adv;
#pragma unroll
        for (int j = 0; j < 8; j++) {
            float l = a[j];
            l = (l > 0.f) ? l : SLOPE * l;
            float w = __expf(l - m);
            den += w;
            acc.x = fmaf(w, hv[j].x, acc.x);
            acc.y = fmaf(w, hv[j].y, acc.y);
            acc.z = fmaf(w, hv[j].z, acc.z);
            acc.w = fmaf(w, hv[j].w, acc.w);
        }
    }
    for (; e < e1; e++) {
        int s = g_csr[e];
        float a = As[s * H + head] + adv;
        a = (a > 0.f) ? a : SLOPE * a;
        float w = __expf(a - m);
        float4 hv = H4[s * 32 + lane];
        den += w;
        acc.x = fmaf(w, hv.x, acc.x);
        acc.y = fmaf(w, hv.y, acc.y);
        acc.z = fmaf(w, hv.z, acc.z);
        acc.w = fmaf(w, hv.w, acc.w);
    }

    float inv = 1.f / den;
    float4 b = ((const float4*)bias)[lane];
    float4 o;
    o.x = acc.x * inv + b.x;
    o.y = acc.y * inv + b.y;
    o.z = acc.z * inv + b.z;
    o.w = acc.w * inv + b.w;
    if (ELU) {
        o.x = (o.x > 0.f) ? o.x : expm1f(o.x);
        o.y = (o.y > 0.f) ? o.y : expm1f(o.y);
        o.z = (o.z > 0.f) ? o.z : expm1f(o.z);
        o.w = (o.w > 0.f) ? o.w : expm1f(o.w);
    }
    ((float4*)out)[warp * 32 + lane] = o;
}

// ---------------- host launcher ----------------
extern "C" void kernel_launch(void* const* d_in, const int* in_sizes, int n_in,
                              void* d_out, int out_size) {
    const float* x   = (const float*)d_in[0];
    const int*   ei  = (const int*)d_in[1];
    const float* W1  = (const float*)d_in[2];
    const float* as1 = (const float*)d_in[3];
    const float* ad1 = (const float*)d_in[4];
    const float* b1  = (const float*)d_in[5];
    const float* W2  = (const float*)d_in[6];
    const float* as2 = (const float*)d_in[7];
    const float* ad2 = (const float*)d_in[8];
    const float* b2  = (const float*)d_in[9];
    const float* W3  = (const float*)d_in[10];
    const float* as3 = (const float*)d_in[11];
    const float* ad3 = (const float*)d_in[12];
    const float* b3  = (const float*)d_in[13];
    const int* src = ei;
    const int* dst = ei + EE;

    const int smem_gemm = (16384 + 8192 + 256) * 4;  // ~97 KB
    cudaFuncSetAttribute(k_gemm<4>, cudaFuncAttributeMaxDynamicSharedMemorySize, smem_gemm);
    cudaFuncSetAttribute(k_gemm<1>, cudaFuncAttributeMaxDynamicSharedMemorySize, smem_gemm);

    float* d_h    = nullptr;
    float* d_feat = nullptr;
    float* d_As   = nullptr;
    float* d_Ad   = nullptr;
    cudaGetSymbolAddress((void**)&d_h, g_h);
    cudaGetSymbolAddress((void**)&d_feat, g_feat);
    cudaGetSymbolAddress((void**)&d_As, g_as);
    cudaGetSymbolAddress((void**)&d_Ad, g_ad);

    // ---- CSR build (by dst) ----
    k_init<<<(NN + 255) / 256, 256>>>();
    k_count<<<(EE + 255) / 256, 256>>>(dst);
    k_scan<<<1, 1024>>>();
    k_scatter<<<(ET + 255) / 256, 256>>>(src, dst);

    const int gemm_blocks = (NN + 63) / 64;           // 1563
    const int node_warp_blocks = (NN * 32 + 255) / 256;  // warp per node

    // ---- layer 1: x -> feat ----
    k_gemm<4><<<gemm_blocks, 128, smem_gemm>>>(x, W1, as1, ad1, d_h, d_As, d_Ad);
    k_agg<4, true><<<node_warp_blocks, 256>>>(d_h, d_As, d_Ad, b1, d_feat);

    // ---- layer 2: feat -> feat ----
    k_gemm<4><<<gemm_blocks, 128, smem_gemm>>>(d_feat, W2, as2, ad2, d_h, d_As, d_Ad);
    k_agg<4, true><<<node_warp_blocks, 256>>>(d_h, d_As, d_Ad, b2, d_feat);

    // ---- layer 3: feat -> out (heads=1, no ELU) ----
    k_gemm<1><<<gemm_blocks, 128, smem_gemm>>>(d_feat, W3, as3, ad3, d_h, d_As, d_Ad);
    k_agg<1, false><<<node_warp_blocks, 256>>>(d_h, d_As, d_Ad, b3, (float*)d_out);
}